// round 17
// baseline (speedup 1.0000x reference)
#include <cuda_runtime.h>
#include <cuda_fp16.h>
#include <math.h>

#define NODES_MAX 100000
#define EDGES_MAX 1200000
#define NEG_SLOPE 0.2f
#define NBLOCKS 740            // 148 SMs x 5 blocks/SM
#define NTHREADS 256
#define TILE 64
#define ASTRIDE 72             // halfs per smem row (padded, conflict-free)
#define CAP 64                 // bucket capacity per node (16B-aligned segments)

// ---------------- static device scratch -------------------------------------
__device__ int    g_counts[NODES_MAX];              // zero-init; re-zeroed in P3
__device__ int    g_csr[NODES_MAX * CAP];           // bucket CSR: node*CAP + [0..count]
__device__ int    g_tile1 = 0;
__device__ int    g_tile2 = 0;
__device__ __half g_h[NODES_MAX * 64];
__device__ __half g_hagg[NODES_MAX * 64];
__device__ float  g_asrc1[NODES_MAX], g_adst1[NODES_MAX];
__device__ float  g_asrc2[NODES_MAX], g_adst2[NODES_MAX];

// ---------------- device-wide barrier ----------------------------------------
__device__ int          g_bar_count = 0;
__device__ volatile int g_bar_gen   = 0;

__device__ __forceinline__ void gbar() {
    __syncthreads();
    if (threadIdx.x == 0) {
        int gen = g_bar_gen;
        __threadfence();
        if (atomicAdd(&g_bar_count, 1) == NBLOCKS - 1) {
            g_bar_count = 0;
            __threadfence();
            g_bar_gen = gen + 1;
        } else {
            while (g_bar_gen == gen) __nanosleep(64);
        }
        __threadfence();
    }
    __syncthreads();
}

__device__ __forceinline__ float leaky_exp(float l) {
    l = (l > 0.0f) ? l : NEG_SLOPE * l;
    return __expf(l);
}

// gather 8 features (fp16) of node sidx at feature base fb, accumulate w*h in fp32
__device__ __forceinline__ void gather_fma(
    const __half* __restrict__ H, int sidx, int fb, float w, float* a)
{
    float4 raw = *(const float4*)&H[sidx * 64 + fb];
    const __half2* hp = (const __half2*)&raw;
    float2 f0 = __half22float2(hp[0]);
    float2 f1 = __half22float2(hp[1]);
    float2 f2 = __half22float2(hp[2]);
    float2 f3 = __half22float2(hp[3]);
    a[0] += w * f0.x; a[1] += w * f0.y;
    a[2] += w * f1.x; a[3] += w * f1.y;
    a[4] += w * f2.x; a[5] += w * f2.y;
    a[6] += w * f3.x; a[7] += w * f3.y;
}

// 4-wide agg inner loop body: int4 index load, 4 weights, 4 gathers in flight
__device__ __forceinline__ void agg_edges(
    const __half* __restrict__ H, const float* __restrict__ asrc,
    int beg, int end, float ad, int fb, float& s, float* a)
{
    int j = beg;
    int cnt4 = (end - beg) & ~3;
    int end4 = beg + cnt4;
    for (; j < end4; j += 4) {
        int4 s4 = *(const int4*)&g_csr[j];          // 16B-aligned (beg % 4 == 0)
        float w0 = leaky_exp(__ldg(&asrc[s4.x]) + ad);
        float w1 = leaky_exp(__ldg(&asrc[s4.y]) + ad);
        float w2 = leaky_exp(__ldg(&asrc[s4.z]) + ad);
        float w3 = leaky_exp(__ldg(&asrc[s4.w]) + ad);
        s += (w0 + w1) + (w2 + w3);
        gather_fma(H, s4.x, fb, w0, a);
        gather_fma(H, s4.y, fb, w1, a);
        gather_fma(H, s4.z, fb, w2, a);
        gather_fma(H, s4.w, fb, w3, a);
    }
    for (; j < end; j++) {
        int s0 = __ldg(&g_csr[j]);
        float w0 = leaky_exp(__ldg(&asrc[s0]) + ad);
        s += w0;
        gather_fma(H, s0, fb, w0, a);
    }
}

// ---------------- HMMA GEMM on one 64x64 tile (A_s fp16 pre-staged) ----------
__device__ __forceinline__ void hmma_tile(
    int base, int n,
    const __half* A_s, const __half* B_s,
    const float* as_s, const float* ad_s,
    float* dotA_buf, float* dotB_buf,
    __half* __restrict__ Hout, float* __restrict__ asrcOut, float* __restrict__ adstOut)
{
    int tid  = threadIdx.x;
    int w    = tid >> 5;
    int lane = tid & 31;
    int g    = lane >> 2;
    int t2   = (lane & 3) * 2;
    int mrow = (w & 3) * 16;
    int ncol = (w >> 2) * 32;

    float acc[4][4];
#pragma unroll
    for (int s = 0; s < 4; s++)
#pragma unroll
        for (int c = 0; c < 4; c++) acc[s][c] = 0.0f;

#pragma unroll
    for (int kk = 0; kk < 4; kk++) {
        int k0 = kk * 16 + t2;
        unsigned a0 = *(const unsigned*)&A_s[(mrow + g) * ASTRIDE + k0];
        unsigned a1 = *(const unsigned*)&A_s[(mrow + g + 8) * ASTRIDE + k0];
        unsigned a2 = *(const unsigned*)&A_s[(mrow + g) * ASTRIDE + k0 + 8];
        unsigned a3 = *(const unsigned*)&A_s[(mrow + g + 8) * ASTRIDE + k0 + 8];
#pragma unroll
        for (int sub = 0; sub < 4; sub++) {
            int nn = ncol + sub * 8 + g;
            unsigned b0 = *(const unsigned*)&B_s[nn * ASTRIDE + k0];
            unsigned b1 = *(const unsigned*)&B_s[nn * ASTRIDE + k0 + 8];
            asm volatile(
                "mma.sync.aligned.m16n8k16.row.col.f32.f16.f16.f32 "
                "{%0,%1,%2,%3}, {%4,%5,%6,%7}, {%8,%9}, {%0,%1,%2,%3};"
                : "+f"(acc[sub][0]), "+f"(acc[sub][1]), "+f"(acc[sub][2]), "+f"(acc[sub][3])
                : "r"(a0), "r"(a1), "r"(a2), "r"(a3), "r"(b0), "r"(b1));
        }
    }

    int row0 = base + mrow + g;
    int row1 = row0 + 8;
    float dA0 = 0.f, dB0 = 0.f, dA1 = 0.f, dB1 = 0.f;
#pragma unroll
    for (int sub = 0; sub < 4; sub++) {
        int c = ncol + sub * 8 + t2;
        float s0 = as_s[c], s1 = as_s[c + 1];
        float e0 = ad_s[c], e1 = ad_s[c + 1];
        dA0 += acc[sub][0] * s0 + acc[sub][1] * s1;
        dB0 += acc[sub][0] * e0 + acc[sub][1] * e1;
        dA1 += acc[sub][2] * s0 + acc[sub][3] * s1;
        dB1 += acc[sub][2] * e0 + acc[sub][3] * e1;
        if (row0 < n) {
            __half2 h = __floats2half2_rn(acc[sub][0], acc[sub][1]);
            *(unsigned*)&Hout[row0 * 64 + c] = *(unsigned*)&h;
        }
        if (row1 < n) {
            __half2 h = __floats2half2_rn(acc[sub][2], acc[sub][3]);
            *(unsigned*)&Hout[row1 * 64 + c] = *(unsigned*)&h;
        }
    }
#pragma unroll
    for (int off = 1; off < 4; off <<= 1) {
        dA0 += __shfl_xor_sync(0xFFFFFFFFu, dA0, off);
        dB0 += __shfl_xor_sync(0xFFFFFFFFu, dB0, off);
        dA1 += __shfl_xor_sync(0xFFFFFFFFu, dA1, off);
        dB1 += __shfl_xor_sync(0xFFFFFFFFu, dB1, off);
    }
    int wc = w >> 2;
    if ((lane & 3) == 0) {
        dotA_buf[wc * 64 + mrow + g] = dA0;
        dotB_buf[wc * 64 + mrow + g] = dB0;
        dotA_buf[wc * 64 + mrow + g + 8] = dA1;
        dotB_buf[wc * 64 + mrow + g + 8] = dB1;
    }
    __syncthreads();
    if (tid < 64) {
        int row = base + tid;
        if (row < n) {
            asrcOut[row] = dotA_buf[tid] + dotA_buf[64 + tid];
            adstOut[row] = dotB_buf[tid] + dotB_buf[64 + tid];
        }
    }
}

// ---------------- the single persistent mega-kernel ---------------------------
__global__ void __launch_bounds__(NTHREADS, 5)
k_mega(const float* __restrict__ x, const int* __restrict__ src, const int* __restrict__ dst,
       int e, int n,
       const float* __restrict__ W1, const float* __restrict__ avs1,
       const float* __restrict__ avd1, const float* __restrict__ b1,
       const float* __restrict__ W2, const float* __restrict__ avs2,
       const float* __restrict__ avd2, const float* __restrict__ b2,
       const float* __restrict__ Wc, const float* __restrict__ bc,
       float* __restrict__ out)
{
    __shared__ __align__(16) __half A_s[TILE * ASTRIDE];
    __shared__ __align__(16) __half B_s[64 * ASTRIDE];
    __shared__ float dotA_buf[2 * 64], dotB_buf[2 * 64];
    __shared__ float as_s[64], ad_s[64];
    __shared__ int tkt;

    int tid = threadIdx.x;
    int gtid = blockIdx.x * NTHREADS + tid;
    const int gstride = NBLOCKS * NTHREADS;
    int ntiles = (n + TILE - 1) / TILE;

    // ---- P1: gemm1 tiles (HMMA) + bucket scatter + self loops ----
    for (int i = tid; i < 4096; i += NTHREADS) {
        int k = i >> 6, nn = i & 63;
        B_s[nn * ASTRIDE + k] = __float2half_rn(W1[i]);
    }
    if (tid < 64) { as_s[tid] = avs1[tid]; ad_s[tid] = avd1[tid]; }

    for (;;) {
        __syncthreads();
        if (tid == 0) tkt = atomicAdd(&g_tile1, 1);
        __syncthreads();
        int t = tkt;
        if (t >= ntiles) break;
        int base = t * TILE;
        for (int it = tid; it < TILE * 32; it += NTHREADS) {
            int r = it >> 5, kc = it & 31;
            int gr = base + r;
            float2 v = (gr < n) ? *(const float2*)&x[gr * 64 + kc * 2] : make_float2(0.f, 0.f);
            __half2 h = __floats2half2_rn(v.x, v.y);
            *(unsigned*)&A_s[r * ASTRIDE + kc * 2] = *(unsigned*)&h;
        }
        __syncthreads();
        hmma_tile(base, n, A_s, B_s, as_s, ad_s, dotA_buf, dotB_buf,
                  g_h, g_asrc1, g_adst1);
    }
    // bucket scatter: slot = d*CAP + 1 + ordinal (self loop reserved at d*CAP)
    for (int i = gtid; i < e; i += gstride) {
        int d = dst[i];
        int r = atomicAdd(&g_counts[d], 1);
        g_csr[d * CAP + 1 + r] = src[i];
    }
    for (int node = gtid; node < n; node += gstride)
        g_csr[node * CAP] = node;                 // self loop first
    gbar();

    // ---- P2: FUSED per-tile [agg1 (4-wide, fp16 gather) -> A_s -> HMMA gemm2] ----
    if (gtid == 0) g_tile1 = 0;                   // replay-safe ticket reset
    __syncthreads();
    for (int i = tid; i < 4096; i += NTHREADS) {
        int k = i >> 6, nn = i & 63;
        B_s[nn * ASTRIDE + k] = __float2half_rn(W2[i]);
    }
    if (tid < 64) { as_s[tid] = avs2[tid]; ad_s[tid] = avd2[tid]; }

    for (;;) {
        __syncthreads();
        if (tid == 0) tkt = atomicAdd(&g_tile2, 1);
        __syncthreads();
        int t = tkt;
        if (t >= ntiles) break;
        int base = t * TILE;

#pragma unroll
        for (int round = 0; round < 2; round++) {
            int item = round * NTHREADS + tid;
            int r = item >> 3;
            int sub = item & 7;
            int node = base + r;
            if (node < n) {
                int beg = node * CAP;
                int end = beg + 1 + g_counts[node];
                float ad = g_adst1[node];
                int fb = sub * 8;
                float s = 0.0f;
                float a[8] = {0.f, 0.f, 0.f, 0.f, 0.f, 0.f, 0.f, 0.f};
                agg_edges(g_h, g_asrc1, beg, end, ad, fb, s, a);
                float inv = 1.0f / (s + 1e-16f);
                float o[8];
#pragma unroll
                for (int k = 0; k < 8; k++)
                    o[k] = fmaxf(a[k] * inv + b1[fb + k], 0.f);
                uint4 u;
                __half2 h0 = __floats2half2_rn(o[0], o[1]);
                __half2 h1 = __floats2half2_rn(o[2], o[3]);
                __half2 h2 = __floats2half2_rn(o[4], o[5]);
                __half2 h3 = __floats2half2_rn(o[6], o[7]);
                u.x = *(unsigned*)&h0; u.y = *(unsigned*)&h1;
                u.z = *(unsigned*)&h2; u.w = *(unsigned*)&h3;
                *(uint4*)&A_s[r * ASTRIDE + fb] = u;
            }
        }
        __syncthreads();
        hmma_tile(base, n, A_s, B_s, as_s, ad_s, dotA_buf, dotB_buf,
                  g_hagg, g_asrc2, g_adst2);
    }
    gbar();

    // ---- P3: agg2 (4-wide) + classifier + log_softmax + counts re-zero ----
    if (gtid == 0) g_tile2 = 0;
    for (int t = gtid; t < n * 8; t += gstride) {
        int node = t >> 3;
        int sub = t & 7;
        int beg = node * CAP;
        int cnt = g_counts[node];                 // converged read across the 8 subs
        int end = beg + 1 + cnt;
        float ad = g_adst2[node];
        int fb = sub * 8;

        float s = 0.0f;
        float a[8] = {0.f, 0.f, 0.f, 0.f, 0.f, 0.f, 0.f, 0.f};
        agg_edges(g_hagg, g_asrc2, beg, end, ad, fb, s, a);

        if (sub == 0) g_counts[node] = 0;         // after the converged read; replay-safe

        float inv = 1.0f / (s + 1e-16f);
        float o[8];
#pragma unroll
        for (int k = 0; k < 8; k++)
            o[k] = fmaxf(a[k] * inv + b2[fb + k], 0.f);

        const float2* Wc2 = (const float2*)Wc;
        float p0 = 0.f, p1 = 0.f;
#pragma unroll
        for (int k = 0; k < 8; k++) {
            float2 wc = __ldg(&Wc2[fb + k]);
            p0 += o[k] * wc.x;
            p1 += o[k] * wc.y;
        }
#pragma unroll
        for (int off = 4; off > 0; off >>= 1) {
            p0 += __shfl_down_sync(0xFFFFFFFFu, p0, off, 8);
            p1 += __shfl_down_sync(0xFFFFFFFFu, p1, off, 8);
        }
        if (sub == 0) {
            float z0 = p0 + bc[0];
            float z1 = p1 + bc[1];
            float mx = fmaxf(z0, z1);
            float lse = mx + logf(expf(z0 - mx) + expf(z1 - mx));
            out[node * 2 + 0] = z0 - lse;
            out[node * 2 + 1] = z1 - lse;
        }
    }
}

// ---------------- launch ------------------------------------------------------
extern "C" void kernel_launch(void* const* d_in, const int* in_sizes, int n_in,
                              void* d_out, int out_size) {
    const float* x      = (const float*)d_in[0];
    const int*   ei     = (const int*)d_in[1];
    const float* W1     = (const float*)d_in[2];
    const float* a_src1 = (const float*)d_in[3];
    const float* a_dst1 = (const float*)d_in[4];
    const float* b1     = (const float*)d_in[5];
    const float* W2     = (const float*)d_in[6];
    const float* a_src2 = (const float*)d_in[7];
    const float* a_dst2 = (const float*)d_in[8];
    const float* b2     = (const float*)d_in[9];
    const float* Wc     = (const float*)d_in[10];
    const float* bc     = (const float*)d_in[11];
    float* out = (float*)d_out;

    const int N = in_sizes[0] / 64;
    const int E = in_sizes[1] / 2;
    const int* src = ei;
    const int* dst = ei + E;

    k_mega<<<NBLOCKS, NTHREADS>>>(x, src, dst, E, N,
                                  W1, a_src1, a_dst1, b1,
                                  W2, a_src2, a_dst2, b2,
                                  Wc, bc, out);
}